// round 5
// baseline (speedup 1.0000x reference)
#include <cuda_runtime.h>

// Izhikevich 6-neuron network, T sequential steps.
// warp0 (tid 0):  LLBN->EBN->IFN recurrence, threshold-shift mux + w~ state (all cycles <=24cyc)
// warp1 (tid 32): TN->MN, same transform, float4 z3 feed
// warp2 (tid 64): 32-lane store warp
// Output: [spikes[5][T] | volts[5][T]]

#define BATCH 32
#define RS_MASK 255
#define RING_BATCHES 8

__device__ __forceinline__ float fset_ge(float a, float th) {
    float r;
    asm("set.ge.f32.f32 %0, %1, %2;" : "=f"(r) : "f"(a), "f"(th));
    return r;
}
__device__ __forceinline__ void st_rel(int* p, int v) {
    asm volatile("st.release.cta.u32 [%0], %1;" :: "l"(p), "r"(v) : "memory");
}
__device__ __forceinline__ int ld_acq(int* p) {
    int v;
    asm volatile("ld.acquire.cta.u32 %0, [%1];" : "=r"(v) : "l"(p) : "memory");
    return v;
}

__global__ void __launch_bounds__(128, 1)
izh_net6(const float* __restrict__ in_mat, int n_mat,
         const float* __restrict__ w12, float* __restrict__ out, int T) {
    __shared__ __align__(16) float ring0[256 * 8];  // z2,z3,z4,_,v2,v3,v4,_
    __shared__ __align__(16) float ring1[256 * 4];  // z5,v5,z6,v6
    __shared__ __align__(16) float ringz[256];      // compact z3 stream
    __shared__ float red[4];
    __shared__ int fl[3];

    const int tid = threadIdx.x;
    if (tid == 0) { fl[0] = 0; fl[1] = 0; fl[2] = 0; }

    // ---- reduction: sum(input_mat) ----
    float s = 0.0f;
    for (int i = tid; i < n_mat; i += 128) s += in_mat[i];
    #pragma unroll
    for (int o = 16; o; o >>= 1) s += __shfl_xor_sync(0xffffffffu, s, o);
    if ((tid & 31) == 0) red[tid >> 5] = s;
    __syncthreads();

    const int nbat = (T + BATCH - 1) / BATCH;

    // ================= warp0 lane0: LLBN -> EBN -> IFN =================
    if (tid == 0) {
        const float total = red[0] + red[1] + red[2] + red[3];
        const float z_plus = total * w12[0];
        // current couplings
        const float A2 = -0.25f * w12[2] * w12[7];   // * z4(t-1)
        const float B2 = 0.25f * w12[3];             // * z2(t-1)
        const float A3 = 0.25f * w12[5];             // * z2(t)
        const float A4 = 0.25f * w12[6];             // * z3(t)
        const float K2 = 35.0f + 0.25f * w12[2] * (z_plus * w12[1]);
        const float K3 = 35.0f + 0.25f * (z_plus * w12[4]);
        const float K4 = 35.0f;
        // shifted thresholds
        const float TH2 = 30.0f - A2, TH3 = 30.0f - A3, TH4 = 30.0f - A4;
        // w~ = K - 0.25u recursion constants:  w' = AL*w + fma(z, fma(-BT,v1,DD), fma(v1,BT,CT))
        // LLBN a=.1 b=-.075 c=-55 d=6:  AL=.975 BT=(-0.25)*(.25*.1*(-.075))=.00046875 d~=-1.5
        const float AL2 = 0.975f,  BT2 = 4.6875e-4f,  CT2 = K2 * 0.025f;
        const float DD2 = -1.5f + BT2 * (-55.0f);
        // EBN a=.02 b=.25 c=-55 d=.05: AL=.995 BT=-3.125e-4 d~=-0.0125
        const float AL3 = 0.995f,  BT3 = -3.125e-4f, CT3 = K3 * 0.005f;
        const float DD3 = -0.0125f + BT3 * (-55.0f);
        // IFN a=.02 b=.25 c=-65 d=6:  AL=.995 BT=-3.125e-4 d~=-1.5
        const float AL4 = 0.995f,  BT4 = -3.125e-4f, CT4 = K4 * 0.005f;
        const float DD4 = -1.5f + BT4 * (-65.0f);

        // state (v, w~), init u2=4.5 u3=u4=-16
        float v2 = -60.0f, w2 = K2 - 0.25f * 4.5f;
        float v3 = -64.0f, w3 = K3 - 0.25f * (-16.0f);
        float v4 = -64.0f, w4 = K4 - 0.25f * (-16.0f);
        float z2p = 0.0f, z4p = 0.0f;
        // cores for step 0
        float core2 = fmaf(v2, fmaf(v2, 0.01f, 2.25f), w2);
        float core3 = fmaf(v3, fmaf(v3, 0.01f, 2.25f), w3);
        float core4 = fmaf(v4, fmaf(v4, 0.01f, 2.25f), w4);

        int si = 0;
        for (int b = 0; b < nbat; ++b) {
            while (b - ld_acq(&fl[2]) >= RING_BATCHES) { }
            const int n = min(BATCH, T - b * BATCH);
            #pragma unroll 4
            for (int i = 0; i < n; ++i, ++si) {
                // ---- LLBN ----
                float base2 = fmaf(z2p, B2, core2);
                float s20 = fset_ge(base2, 30.0f);
                float s21 = fset_ge(base2, TH2);
                float d2  = s21 - s20;
                float z2  = fmaf(z4p, d2, s20);
                float v12 = fmaf(z4p, A2, base2);
                float dv2 = -55.0f - v12;
                float nv2 = fmaf(z2, dv2, v12);
                float t12 = fmaf(v12, BT2, CT2);
                float dt2 = fmaf(v12, -BT2, DD2);
                w2 = fmaf(AL2, w2, fmaf(z2, dt2, t12));
                core2 = fmaf(nv2, fmaf(nv2, 0.01f, 2.25f), w2);
                v2 = nv2;
                // ---- EBN ----
                float s30 = fset_ge(core3, 30.0f);
                float s31 = fset_ge(core3, TH3);
                float d3  = s31 - s30;
                float z3  = fmaf(z2, d3, s30);
                float v13 = fmaf(z2, A3, core3);
                float dv3 = -55.0f - v13;
                float nv3 = fmaf(z3, dv3, v13);
                float t13 = fmaf(v13, BT3, CT3);
                float dt3 = fmaf(v13, -BT3, DD3);
                w3 = fmaf(AL3, w3, fmaf(z3, dt3, t13));
                core3 = fmaf(nv3, fmaf(nv3, 0.01f, 2.25f), w3);
                v3 = nv3;
                // ---- IFN ----
                float s40 = fset_ge(core4, 30.0f);
                float s41 = fset_ge(core4, TH4);
                float d4  = s41 - s40;
                float z4  = fmaf(z3, d4, s40);
                float v14 = fmaf(z3, A4, core4);
                float dv4 = -65.0f - v14;
                float nv4 = fmaf(z4, dv4, v14);
                float t14 = fmaf(v14, BT4, CT4);
                float dt4 = fmaf(v14, -BT4, DD4);
                w4 = fmaf(AL4, w4, fmaf(z4, dt4, t14));
                core4 = fmaf(nv4, fmaf(nv4, 0.01f, 2.25f), w4);
                v4 = nv4;

                z2p = z2; z4p = z4;
                // publish
                const int idx = (si & RS_MASK) * 8;
                *reinterpret_cast<float4*>(&ring0[idx])     = make_float4(z2, z3, z4, 0.0f);
                *reinterpret_cast<float4*>(&ring0[idx + 4]) = make_float4(v2, v3, v4, 0.0f);
                ringz[si & RS_MASK] = z3;
            }
            st_rel(&fl[0], b + 1);
        }
        return;
    }

    // ================= warp1 lane0: TN -> MN =================
    if (tid == 32) {
        const float A5 = 0.25f * w12[9] * w12[8];  // * z3(t)
        const float B5 = 0.25f * w12[10];          // * z5(t-1)
        const float A6 = 0.25f * w12[11];          // * z5(t)
        // TN a=.02 b=.2 c=-65 d=6:  AL=.995 BT=-0.25*(.25*.02*.2)=-2.5e-4 d~=-1.5
        const float AL5 = 0.995f, BT5 = -2.5e-4f,   CT5 = 35.0f * 0.005f;
        const float DD5 = -1.5f + BT5 * (-65.0f);
        // MN a=.02 b=.25 c=-65 d=6
        const float AL6 = 0.995f, BT6 = -3.125e-4f, CT6 = 35.0f * 0.005f;
        const float DD6 = -1.5f + BT6 * (-65.0f);

        float v5 = -70.0f, w5 = 35.0f - 0.25f * (-14.0f);
        float v6 = -64.0f, w6 = 35.0f - 0.25f * (-16.0f);
        float z5p = 0.0f;
        float core5 = fmaf(v5, fmaf(v5, 0.01f, 2.25f), w5);
        float core6 = fmaf(v6, fmaf(v6, 0.01f, 2.25f), w6);

        int si = 0;
        for (int b = 0; b < nbat; ++b) {
            while (ld_acq(&fl[0]) <= b) { }
            const int n = min(BATCH, T - b * BATCH);
            for (int i4 = 0; i4 < n; i4 += 4) {
                // whole batch is published: bulk-load 4 z3s (aligned: si%4==0)
                float4 zq = *reinterpret_cast<float4*>(&ringz[si & RS_MASK]);
                float z3v[4] = {zq.x, zq.y, zq.z, zq.w};
                #pragma unroll
                for (int j = 0; j < 4; ++j, ++si) {
                    float z3 = z3v[j];
                    // ---- TN ----
                    float base5 = fmaf(z3, A5, core5);
                    float v15 = fmaf(z5p, B5, base5);
                    float z5 = fset_ge(v15, 30.0f);
                    float dv5 = -65.0f - v15;
                    float nv5 = fmaf(z5, dv5, v15);
                    float t15 = fmaf(v15, BT5, CT5);
                    float dt5 = fmaf(v15, -BT5, DD5);
                    w5 = fmaf(AL5, w5, fmaf(z5, dt5, t15));
                    core5 = fmaf(nv5, fmaf(nv5, 0.01f, 2.25f), w5);
                    v5 = nv5;
                    // ---- MN ----
                    float v16 = fmaf(z5, A6, core6);
                    float z6 = fset_ge(v16, 30.0f);
                    float dv6 = -65.0f - v16;
                    float nv6 = fmaf(z6, dv6, v16);
                    float t16 = fmaf(v16, BT6, CT6);
                    float dt6 = fmaf(v16, -BT6, DD6);
                    w6 = fmaf(AL6, w6, fmaf(z6, dt6, t16));
                    core6 = fmaf(nv6, fmaf(nv6, 0.01f, 2.25f), w6);
                    v6 = nv6;

                    z5p = z5;
                    *reinterpret_cast<float4*>(&ring1[(si & RS_MASK) * 4]) =
                        make_float4(z5, v5, z6, v6);
                }
            }
            st_rel(&fl[1], b + 1);
        }
        return;
    }

    // ================= warp2: store warp =================
    if (tid >= 64 && tid < 96) {
        const int lane = tid - 64;
        // rows: z2 z3 z4 z5 z6 v2 v3 v4 v5 v6
        // buf:   0  0  0  1  1  0  0  0  1  1   (mask 0x318)
        // col:   0  1  2  0  2  4  5  6  1  3
        for (int b = 0; b < nbat; ++b) {
            while (ld_acq(&fl[1]) <= b) { }
            const int base = b * BATCH;
            const int n = min(BATCH, T - base);
            if ((T & 3) == 0) {
                const int quads = n >> 2;
                const int units = 10 * quads;
                for (int u = lane; u < units; u += 32) {
                    const int row = u / quads;
                    const int q   = u - row * quads;
                    const int st  = base + q * 4;
                    const int buf = (0x318 >> row) & 1;
                    const int col = (row < 8) ? ((0x65420210u >> (4 * row)) & 15)
                                              : ((0x31u >> (4 * (row - 8))) & 15);
                    float x0, x1, x2, x3;
                    if (buf == 0) {
                        x0 = ring0[((st + 0) & RS_MASK) * 8 + col];
                        x1 = ring0[((st + 1) & RS_MASK) * 8 + col];
                        x2 = ring0[((st + 2) & RS_MASK) * 8 + col];
                        x3 = ring0[((st + 3) & RS_MASK) * 8 + col];
                    } else {
                        x0 = ring1[((st + 0) & RS_MASK) * 4 + col];
                        x1 = ring1[((st + 1) & RS_MASK) * 4 + col];
                        x2 = ring1[((st + 2) & RS_MASK) * 4 + col];
                        x3 = ring1[((st + 3) & RS_MASK) * 4 + col];
                    }
                    *reinterpret_cast<float4*>(&out[row * T + st]) =
                        make_float4(x0, x1, x2, x3);
                }
            } else {
                const int units = 10 * n;
                for (int u = lane; u < units; u += 32) {
                    const int row = u / n;
                    const int i   = u - row * n;
                    const int st  = base + i;
                    const int buf = (0x318 >> row) & 1;
                    const int col = (row < 8) ? ((0x65420210u >> (4 * row)) & 15)
                                              : ((0x31u >> (4 * (row - 8))) & 15);
                    float x = buf ? ring1[(st & RS_MASK) * 4 + col]
                                  : ring0[(st & RS_MASK) * 8 + col];
                    out[row * T + st] = x;
                }
            }
            __syncwarp();
            if (lane == 0) st_rel(&fl[2], b + 1);
        }
        return;
    }
}

extern "C" void kernel_launch(void* const* d_in, const int* in_sizes, int n_in,
                              void* d_out, int out_size) {
    const float* in_mat = (const float*)d_in[0];
    const float* w12    = (const float*)d_in[1];
    int n_mat = in_sizes[0];
    int T = out_size / 10;
    izh_net6<<<1, 128>>>(in_mat, n_mat, w12, (float*)d_out, T);
}